// round 6
// baseline (speedup 1.0000x reference)
#include <cuda_runtime.h>

// CircleProjectionLayer: z = center + (x-center) * min(1, 1/||x-center||)
// B = 8388608 points, [B,3] f32. HBM stream: 192MB read + 96MB write.
//
// R6: isolate R2's confound. 8 points/thread (12 front-batched LDG.128,
// then 6 STG.128) with DEFAULT caching (no __ldcs/__stcs). Goal: longer
// same-direction DRAM bursts to cut read<->write bus turnaround, which is
// the leading explanation for R1's 27% DRAM idle.

__global__ void __launch_bounds__(256)
circle_proj_kernel(const float4* __restrict__ x4,
                   const float4* __restrict__ c4,
                   float4* __restrict__ o4,
                   int n_groups)  // groups of 8 points = 6 float4 each
{
    int i = blockIdx.x * blockDim.x + threadIdx.x;
    if (i >= n_groups) return;

    long base = 6L * i;

    // Front-batch all 12 loads (long read burst) before any math.
    float4 xv[6], cv[6];
#pragma unroll
    for (int k = 0; k < 6; k++) xv[k] = x4[base + k];
#pragma unroll
    for (int k = 0; k < 6; k++) cv[k] = c4[base + k];

    float xs[24], cs[24], os[24];
#pragma unroll
    for (int k = 0; k < 6; k++) {
        xs[4 * k + 0] = xv[k].x; xs[4 * k + 1] = xv[k].y;
        xs[4 * k + 2] = xv[k].z; xs[4 * k + 3] = xv[k].w;
        cs[4 * k + 0] = cv[k].x; cs[4 * k + 1] = cv[k].y;
        cs[4 * k + 2] = cv[k].z; cs[4 * k + 3] = cv[k].w;
    }

#pragma unroll
    for (int p = 0; p < 8; p++) {
        float dx = xs[3 * p + 0] - cs[3 * p + 0];
        float dy = xs[3 * p + 1] - cs[3 * p + 1];
        float dz = xs[3 * p + 2] - cs[3 * p + 2];
        float n2 = fmaf(dx, dx, fmaf(dy, dy, dz * dz));
        // RADIUS = 1: scale = min(1, 1/||d||); rsqrtf(0)=inf -> scale=1 -> z=x.
        float s = fminf(1.0f, rsqrtf(n2));
        os[3 * p + 0] = fmaf(dx, s, cs[3 * p + 0]);
        os[3 * p + 1] = fmaf(dy, s, cs[3 * p + 1]);
        os[3 * p + 2] = fmaf(dz, s, cs[3 * p + 2]);
    }

    // Long write burst.
#pragma unroll
    for (int k = 0; k < 6; k++) {
        o4[base + k] = make_float4(os[4 * k + 0], os[4 * k + 1],
                                   os[4 * k + 2], os[4 * k + 3]);
    }
}

extern "C" void kernel_launch(void* const* d_in, const int* in_sizes, int n_in,
                              void* d_out, int out_size)
{
    const float4* x4 = (const float4*)d_in[0];   // x: [B,3] f32
    const float4* c4 = (const float4*)d_in[1];   // center: [B,3] f32
    float4* o4 = (float4*)d_out;

    int n_elems = in_sizes[0];          // B*3 = 25165824
    int n_points = n_elems / 3;         // 8388608
    int n_groups = n_points / 8;        // 1048576

    int threads = 256;
    int blocks = (n_groups + threads - 1) / threads;  // 4096
    circle_proj_kernel<<<blocks, threads>>>(x4, c4, o4, n_groups);
}

// round 7
// speedup vs baseline: 1.2528x; 1.2528x over previous
#include <cuda_runtime.h>

// CircleProjectionLayer: z = center + (x-center) * min(1, 1/||x-center||)
// B = 8388608 points, [B,3] f32. HBM stream: 192MB read + 96MB write.
//
// R7: R1 structure exactly (4 points/thread = 3 x LDG.128 per input at 48B
// lane stride — proven sweet spot) + __ldcg loads (no L1 allocate). Zero-
// reuse stream: skip L1 fill/tag work, identical L2/DRAM sector stream.

__global__ void __launch_bounds__(256)
circle_proj_kernel(const float4* __restrict__ x4,
                   const float4* __restrict__ c4,
                   float4* __restrict__ o4,
                   int n_quads)  // groups of 4 points = 3 float4 each
{
    int i = blockIdx.x * blockDim.x + threadIdx.x;
    if (i >= n_quads) return;

    long base = 3L * i;

    // Front-batch all 6 loads (MLP=6) before any math. L2-only caching.
    float4 xa = __ldcg(&x4[base + 0]);
    float4 xb = __ldcg(&x4[base + 1]);
    float4 xc = __ldcg(&x4[base + 2]);
    float4 ca = __ldcg(&c4[base + 0]);
    float4 cb = __ldcg(&c4[base + 1]);
    float4 cc = __ldcg(&c4[base + 2]);

    float xs[12] = {xa.x, xa.y, xa.z, xa.w,
                    xb.x, xb.y, xb.z, xb.w,
                    xc.x, xc.y, xc.z, xc.w};
    float cs[12] = {ca.x, ca.y, ca.z, ca.w,
                    cb.x, cb.y, cb.z, cb.w,
                    cc.x, cc.y, cc.z, cc.w};
    float os[12];

#pragma unroll
    for (int p = 0; p < 4; p++) {
        float dx = xs[3 * p + 0] - cs[3 * p + 0];
        float dy = xs[3 * p + 1] - cs[3 * p + 1];
        float dz = xs[3 * p + 2] - cs[3 * p + 2];
        float n2 = fmaf(dx, dx, fmaf(dy, dy, dz * dz));
        // RADIUS = 1: scale = min(1, 1/||d||); rsqrtf(0)=inf -> scale=1 -> z=x.
        float s = fminf(1.0f, rsqrtf(n2));
        os[3 * p + 0] = fmaf(dx, s, cs[3 * p + 0]);
        os[3 * p + 1] = fmaf(dy, s, cs[3 * p + 1]);
        os[3 * p + 2] = fmaf(dz, s, cs[3 * p + 2]);
    }

    o4[base + 0] = make_float4(os[0], os[1], os[2],  os[3]);
    o4[base + 1] = make_float4(os[4], os[5], os[6],  os[7]);
    o4[base + 2] = make_float4(os[8], os[9], os[10], os[11]);
}

extern "C" void kernel_launch(void* const* d_in, const int* in_sizes, int n_in,
                              void* d_out, int out_size)
{
    const float4* x4 = (const float4*)d_in[0];   // x: [B,3] f32
    const float4* c4 = (const float4*)d_in[1];   // center: [B,3] f32
    float4* o4 = (float4*)d_out;

    int n_elems = in_sizes[0];          // B*3 = 25165824
    int n_points = n_elems / 3;         // 8388608
    int n_quads = n_points / 4;         // 2097152

    int threads = 256;
    int blocks = (n_quads + threads - 1) / threads;  // 8192
    circle_proj_kernel<<<blocks, threads>>>(x4, c4, o4, n_quads);
}